// round 1
// baseline (speedup 1.0000x reference)
#include <cuda_runtime.h>
#include <cstdint>

#define NB 8192      // batch
#define NA 128       // attr dim
#define NH 256       // hidden
#define NV 64        // vocab
#define NL 20        // rollout length
#define G4 (4*NH)    // 1024 gate columns

// ---------------- device scratch (static; no runtime allocation) ----------------
__device__ float g_h[NB*NH];
__device__ float g_c[NB*NH];
__device__ float g_gates[NB*G4];
__device__ int   g_ch[NB];
__device__ float g_slp[NB];
__device__ float g_plp[NB];
__device__ float g_ep[NB];

// ---------------- Threefry-2x32 (20 rounds), matches JAX exactly ----------------
__host__ __device__ __forceinline__ uint32_t rotl32(uint32_t x, int r) {
    return (x << r) | (x >> (32 - r));
}

__host__ __device__ __forceinline__ void threefry2x32(
    uint32_t k0, uint32_t k1, uint32_t x0, uint32_t x1,
    uint32_t& o0, uint32_t& o1)
{
    uint32_t ks0 = k0, ks1 = k1, ks2 = k0 ^ k1 ^ 0x1BD11BDAu;
    x0 += ks0; x1 += ks1;
#define TF_RND(r) { x0 += x1; x1 = rotl32(x1, (r)); x1 ^= x0; }
    TF_RND(13) TF_RND(15) TF_RND(26) TF_RND(6)
    x0 += ks1; x1 += ks2 + 1u;
    TF_RND(17) TF_RND(29) TF_RND(16) TF_RND(24)
    x0 += ks2; x1 += ks0 + 2u;
    TF_RND(13) TF_RND(15) TF_RND(26) TF_RND(6)
    x0 += ks0; x1 += ks1 + 3u;
    TF_RND(17) TF_RND(29) TF_RND(16) TF_RND(24)
    x0 += ks1; x1 += ks2 + 4u;
    TF_RND(13) TF_RND(15) TF_RND(26) TF_RND(6)
    x0 += ks2; x1 += ks0 + 5u;
#undef TF_RND
    o0 = x0; o1 = x1;
}

// ---------------- init: c=0, slp=0, plp=0, ep=1 ----------------
__global__ void init_kernel() {
    int i = blockIdx.x * blockDim.x + threadIdx.x;
    if (i < NB*NH) g_c[i] = 0.0f;
    if (i < NB) { g_slp[i] = 0.0f; g_plp[i] = 0.0f; g_ep[i] = 1.0f; }
}

// ---------------- generic GEMM: C[m,n] = sum_k A[m,k]*B[n,k] + bias (+ one-hot gather) ----------------
// B is row-major [N, K] (i.e. we compute A @ B^T). Tiles: 64x64x32, 256 threads, 4x4 microtile.
__global__ __launch_bounds__(256) void gemm_bias(
    const float* __restrict__ A, const float* __restrict__ Bm,
    const float* __restrict__ bias1, const float* __restrict__ bias2,
    const float* __restrict__ Wih, const int* __restrict__ ch,
    float* __restrict__ C, int N, int K, int useX)
{
    __shared__ float Asm[32][64];   // [k][m]
    __shared__ float Bsm[32][64];   // [k][n]
    const int bm = blockIdx.y * 64;
    const int bn = blockIdx.x * 64;
    const int tid = threadIdx.x;
    const int tx = tid & 15, ty = tid >> 4;

    float acc[4][4];
#pragma unroll
    for (int i = 0; i < 4; i++)
#pragma unroll
        for (int j = 0; j < 4; j++) acc[i][j] = 0.0f;

    for (int k0 = 0; k0 < K; k0 += 32) {
#pragma unroll
        for (int r = 0; r < 8; r++) {
            int idx = tid + r * 256;
            int m = idx >> 5, kk = idx & 31;
            Asm[kk][m] = A[(size_t)(bm + m) * K + k0 + kk];
        }
#pragma unroll
        for (int r = 0; r < 8; r++) {
            int idx = tid + r * 256;
            int n = idx >> 5, kk = idx & 31;
            Bsm[kk][n] = Bm[(size_t)(bn + n) * K + k0 + kk];
        }
        __syncthreads();
#pragma unroll
        for (int kk = 0; kk < 32; kk++) {
            float a[4], b[4];
#pragma unroll
            for (int i = 0; i < 4; i++) a[i] = Asm[kk][ty * 4 + i];
#pragma unroll
            for (int j = 0; j < 4; j++) b[j] = Bsm[kk][tx * 4 + j];
#pragma unroll
            for (int i = 0; i < 4; i++)
#pragma unroll
                for (int j = 0; j < 4; j++) acc[i][j] = fmaf(a[i], b[j], acc[i][j]);
        }
        __syncthreads();
    }

#pragma unroll
    for (int i = 0; i < 4; i++) {
        int m = bm + ty * 4 + i;
        int chm = useX ? ch[m] : 0;
#pragma unroll
        for (int j = 0; j < 4; j++) {
            int n = bn + tx * 4 + j;
            float v = acc[i][j] + bias1[n];
            if (bias2) v += bias2[n];
            if (useX) v += Wih[(size_t)n * NV + chm];
            C[(size_t)m * N + n] = v;
        }
    }
}

// ---------------- elementwise LSTM cell update ----------------
__device__ __forceinline__ float sigf(float x) { return 1.0f / (1.0f + expf(-x)); }

__global__ void lstm_update() {
    int i = blockIdx.x * blockDim.x + threadIdx.x;
    if (i >= NB*NH) return;
    int b = i >> 8, hh = i & 255;
    const float* gr = g_gates + (size_t)b * G4;
    float gi = gr[hh], gf = gr[NH + hh], gg = gr[2*NH + hh], go = gr[3*NH + hh];
    float cn = sigf(gf) * g_c[i] + sigf(gi) * tanhf(gg);
    float hn = sigf(go) * tanhf(cn);
    g_c[i] = cn;
    g_h[i] = hn;
}

// ---------------- per-row: logits, log_softmax stats, Gumbel-argmax sample ----------------
// one block per batch row, 64 threads (one per vocab entry)
__global__ __launch_bounds__(64) void sample_kernel(
    const float* __restrict__ Wv, const float* __restrict__ bv,
    float* __restrict__ out, int t, uint32_t sk0, uint32_t sk1)
{
    const int b = blockIdx.x;
    const int v = threadIdx.x;
    const int lane = v & 31, warp = v >> 5;

    __shared__ float hrow[NH];
    __shared__ float s_logp[NV];
    __shared__ float s_max[2], s_sum[2], s_plp[2];
    __shared__ float s_zz[2];
    __shared__ int   s_zi[2];

    for (int i = v; i < NH; i += 64) hrow[i] = g_h[(size_t)b * NH + i];
    __syncthreads();

    // logits
    float acc = bv[v];
    const float* w = Wv + (size_t)v * NH;
#pragma unroll 8
    for (int k = 0; k < NH; k++) acc = fmaf(hrow[k], __ldg(w + k), acc);

    // max over 64
    float wm = acc;
#pragma unroll
    for (int o = 16; o; o >>= 1) wm = fmaxf(wm, __shfl_xor_sync(0xffffffffu, wm, o));
    if (lane == 0) s_max[warp] = wm;
    __syncthreads();
    float m = fmaxf(s_max[0], s_max[1]);

    // sum exp(l - m)
    float e = expf(acc - m);
    float ws = e;
#pragma unroll
    for (int o = 16; o; o >>= 1) ws += __shfl_xor_sync(0xffffffffu, ws, o);
    if (lane == 0) s_sum[warp] = ws;
    __syncthreads();
    float lse = logf(s_sum[0] + s_sum[1]);
    float logp = (acc - m) - lse;
    s_logp[v] = logp;

    // plp term: sum_v exp(logp)*logp
    float pt = expf(logp) * logp;
#pragma unroll
    for (int o = 16; o; o >>= 1) pt += __shfl_xor_sync(0xffffffffu, pt, o);
    if (lane == 0) s_plp[warp] = pt;

    // Gumbel noise (JAX partitionable threefry path):
    // bits[i] = x0 ^ x1 of threefry(subkey, (hi32(i), lo32(i))), i = b*V + v
    uint32_t o0, o1;
    threefry2x32(sk0, sk1, 0u, (uint32_t)(b * NV + v), o0, o1);
    uint32_t bits = o0 ^ o1;
    float f = __uint_as_float((bits >> 9) | 0x3f800000u) - 1.0f;
    const float TINY = 1.17549435e-38f;
    float u = fmaxf(TINY, f * (1.0f - TINY) + TINY);
    float g = -logf(-logf(u));
    float z = acc + g;

    // argmax over 64 with first-index tie-break
    int idx = v;
#pragma unroll
    for (int o = 16; o; o >>= 1) {
        float oz = __shfl_xor_sync(0xffffffffu, z, o);
        int   oi = __shfl_xor_sync(0xffffffffu, idx, o);
        if (oz > z || (oz == z && oi < idx)) { z = oz; idx = oi; }
    }
    if (lane == 0) { s_zz[warp] = z; s_zi[warp] = idx; }
    __syncthreads();

    if (v == 0) {
        int chb;
        if (s_zz[1] > s_zz[0]) chb = s_zi[1];
        else if (s_zz[0] > s_zz[1]) chb = s_zi[0];
        else chb = min(s_zi[0], s_zi[1]);
        float lp = s_logp[chb];
        g_ch[b] = chb;
        g_slp[b] += lp;
        g_plp[b] += s_plp[0] + s_plp[1];
        g_ep[b]  *= expf(lp);
        out[(size_t)b * NL + t] = (float)chb;   // message[b, t]
    }
}

__global__ void finalize_kernel(float* __restrict__ out) {
    int b = blockIdx.x * blockDim.x + threadIdx.x;
    if (b < NB) {
        out[NB*NL + b]          = g_slp[b];
        out[NB*NL + NB + b]     = g_plp[b];
        out[NB*NL + 2*NB + b]   = g_ep[b];
    }
}

// ---------------- launcher ----------------
extern "C" void kernel_launch(void* const* d_in, const int* in_sizes, int n_in,
                              void* d_out, int out_size)
{
    const float* attr = (const float*)d_in[0];
    const float* W_a  = (const float*)d_in[1];
    const float* b_a  = (const float*)d_in[2];
    const float* W_ih = (const float*)d_in[3];
    const float* W_hh = (const float*)d_in[4];
    const float* b_ih = (const float*)d_in[5];
    const float* b_hh = (const float*)d_in[6];
    const float* W_v  = (const float*)d_in[7];
    const float* b_v  = (const float*)d_in[8];
    float* out = (float*)d_out;

    float *ph, *pg; int* pch;
    cudaGetSymbolAddress((void**)&ph,  g_h);
    cudaGetSymbolAddress((void**)&pg,  g_gates);
    cudaGetSymbolAddress((void**)&pch, g_ch);

    init_kernel<<<(NB*NH + 255)/256, 256>>>();

    // h0 = attr @ W_a^T + b_a
    gemm_bias<<<dim3(NH/64, NB/64), 256>>>(attr, W_a, b_a, nullptr, nullptr, nullptr,
                                           ph, NH, NA, 0);

    // start-token LSTM step (x = 0): gates = h @ W_hh^T + b_ih + b_hh
    gemm_bias<<<dim3(G4/64, NB/64), 256>>>(ph, W_hh, b_ih, b_hh, nullptr, nullptr,
                                           pg, G4, NH, 0);
    lstm_update<<<(NB*NH + 255)/256, 256>>>();

    // subkeys: JAX fold-like split -> subkey_t = threefry(key(42)=(0,42), (0, t))
    for (int t = 0; t < NL; t++) {
        uint32_t s0, s1;
        threefry2x32(0u, 42u, 0u, (uint32_t)t, s0, s1);
        sample_kernel<<<NB, 64>>>(W_v, b_v, out, t, s0, s1);
        // gates = onehot(ch) @ W_ih^T + h @ W_hh^T + b_ih + b_hh  (one-hot = column gather)
        gemm_bias<<<dim3(G4/64, NB/64), 256>>>(ph, W_hh, b_ih, b_hh, W_ih, pch,
                                               pg, G4, NH, 1);
        lstm_update<<<(NB*NH + 255)/256, 256>>>();
    }

    finalize_kernel<<<(NB + 255)/256, 256>>>(out);
}

// round 2
// speedup vs baseline: 5.4098x; 5.4098x over previous
#include <cuda_runtime.h>
#include <cstdint>

#define NB 8192      // batch
#define NA 128       // attr dim
#define NH 256       // hidden
#define NV 64        // vocab
#define NL 20        // rollout length
#define NBR 56       // batch rows per block
#define NBLK 147     // ceil(NB/NBR)
#define NT 512       // threads per block
#define HP 57        // padded b-stride for h/c smem

// ---- shared memory layout (float offsets) ----
#define OFF_HA 0
#define OFF_HB (NH*HP)                 // 14592
#define OFF_CS (2*NH*HP)               // 29184
#define OFF_WT (3*NH*HP)               // 43776 (8320 floats: 32x260 or 128x65)
#define OFF_LOGP (OFF_WT + 8320)       // 52096 (8 bg x 64 v)
#define OFF_RMAX (OFF_LOGP + 512)
#define OFF_RSUM (OFF_RMAX + 16)
#define OFF_RPLP (OFF_RSUM + 16)
#define OFF_RZ   (OFF_RPLP + 16)
#define OFF_RI   (OFF_RZ + 16)         // int
#define OFF_CH   (OFF_RI + 16)         // int[56]
#define OFF_SLP  (OFF_CH + 56)
#define OFF_PLP  (OFF_SLP + 56)
#define OFF_EP   (OFF_PLP + 56)
#define SMEM_FLOATS (OFF_EP + 56)      // 52912 floats = 211,648 B

// ---- reordered weight scratch (static device arrays) ----
__device__ float g_WhhR[4*65536];   // [chunk][k 256][nloc 256], nloc = gate*64+hl
__device__ float g_WihR[64*1024];   // [ch][chunk*256 + gate*64 + hl]
__device__ float g_WaR[4*8192];     // [chunk][k 128][hl 64]
__device__ float g_biasR[1024];     // [chunk*256 + gate*64 + hl] = b_ih+b_hh

struct Keys { unsigned int a[NL]; unsigned int b[NL]; };

// ---------------- Threefry-2x32 (20 rounds), matches JAX ----------------
__host__ __device__ __forceinline__ uint32_t rotl32(uint32_t x, int r) {
    return (x << r) | (x >> (32 - r));
}
__host__ __device__ __forceinline__ void threefry2x32(
    uint32_t k0, uint32_t k1, uint32_t x0, uint32_t x1,
    uint32_t& o0, uint32_t& o1)
{
    uint32_t ks0 = k0, ks1 = k1, ks2 = k0 ^ k1 ^ 0x1BD11BDAu;
    x0 += ks0; x1 += ks1;
#define TF_RND(r) { x0 += x1; x1 = rotl32(x1, (r)); x1 ^= x0; }
    TF_RND(13) TF_RND(15) TF_RND(26) TF_RND(6)
    x0 += ks1; x1 += ks2 + 1u;
    TF_RND(17) TF_RND(29) TF_RND(16) TF_RND(24)
    x0 += ks2; x1 += ks0 + 2u;
    TF_RND(13) TF_RND(15) TF_RND(26) TF_RND(6)
    x0 += ks0; x1 += ks1 + 3u;
    TF_RND(17) TF_RND(29) TF_RND(16) TF_RND(24)
    x0 += ks1; x1 += ks2 + 4u;
    TF_RND(13) TF_RND(15) TF_RND(26) TF_RND(6)
    x0 += ks2; x1 += ks0 + 5u;
#undef TF_RND
    o0 = x0; o1 = x1;
}

__device__ __forceinline__ float sigf(float x) { return 1.0f / (1.0f + expf(-x)); }

// ---------------- prep: reorder weights for coalesced tiled access ----------------
__global__ void prep_kernel(const float* __restrict__ Whh, const float* __restrict__ Wih,
                            const float* __restrict__ Wa,  const float* __restrict__ bih,
                            const float* __restrict__ bhh)
{
    int idx = blockIdx.x * blockDim.x + threadIdx.x;
    if (idx < 4*65536) {
        int c = idx >> 16, r = idx & 65535, k = r >> 8, n = r & 255;
        int g = n >> 6, hl = n & 63;
        g_WhhR[idx] = Whh[(size_t)(g*256 + c*64 + hl) * 256 + k];
    }
    if (idx < 64*1024) {
        int ch = idx >> 10, low = idx & 1023;
        int c = low >> 8, g = (low >> 6) & 3, hl = low & 63;
        g_WihR[idx] = Wih[(size_t)(g*256 + c*64 + hl) * 64 + ch];
    }
    if (idx < 4*8192) {
        int c = idx >> 13, r = idx & 8191, k = r >> 6, hl = r & 63;
        g_WaR[idx] = Wa[(size_t)(c*64 + hl) * 128 + k];
    }
    if (idx < 1024) {
        int c = idx >> 8, g = (idx >> 6) & 3, hl = idx & 63;
        int gn = g*256 + c*64 + hl;
        g_biasR[idx] = bih[gn] + bhh[gn];
    }
}

// ---------------- one LSTM step: gates GEMM + cell update ----------------
__device__ __forceinline__ void lstm_step(float* sm, const float* hcur, float* hnew,
                                          int tid, int bq, int hl, bool hasX)
{
    const int b0 = bq * 7;
    for (int c = 0; c < 4; c++) {
        float acc[7][4];
#pragma unroll
        for (int i = 0; i < 7; i++)
#pragma unroll
            for (int g = 0; g < 4; g++) acc[i][g] = 0.0f;

        const float* Wg = g_WhhR + c * 65536;
        float4 pf[4];
#pragma unroll
        for (int s = 0; s < 4; s++) {
            int idx = tid + s * NT;
            int kk = idx >> 6, f4 = idx & 63;
            pf[s] = ((const float4*)(Wg + kk * 256))[f4];
        }
        for (int kt = 0; kt < 8; kt++) {
#pragma unroll
            for (int s = 0; s < 4; s++) {
                int idx = tid + s * NT;
                int kk = idx >> 6, f4 = idx & 63;
                ((float4*)(sm + OFF_WT))[kk * 65 + f4] = pf[s];
            }
            __syncthreads();
            if (kt < 7) {
#pragma unroll
                for (int s = 0; s < 4; s++) {
                    int idx = tid + s * NT;
                    int kk = idx >> 6, f4 = idx & 63;
                    pf[s] = ((const float4*)(Wg + ((kt + 1) * 32 + kk) * 256))[f4];
                }
            }
            const float* hk = hcur + kt * 32 * HP + b0;
            const float* wk = sm + OFF_WT + hl;
#pragma unroll 8
            for (int kk = 0; kk < 32; kk++) {
                float hv[7], wv[4];
#pragma unroll
                for (int i = 0; i < 7; i++) hv[i] = hk[kk * HP + i];
#pragma unroll
                for (int g = 0; g < 4; g++) wv[g] = wk[kk * 260 + g * 64];
#pragma unroll
                for (int i = 0; i < 7; i++)
#pragma unroll
                    for (int g = 0; g < 4; g++)
                        acc[i][g] = fmaf(hv[i], wv[g], acc[i][g]);
            }
            __syncthreads();
        }
        // epilogue: gates -> c,h for hidden units [c*64 + hl]
        const int hh = c * 64 + hl;
        float bb[4];
#pragma unroll
        for (int g = 0; g < 4; g++) bb[g] = g_biasR[c*256 + g*64 + hl];
        const int* s_ch = (const int*)sm + OFF_CH;
#pragma unroll
        for (int i = 0; i < 7; i++) {
            int b = b0 + i;
            float xg[4] = {0.f, 0.f, 0.f, 0.f};
            if (hasX) {
                int ch = s_ch[b];
                const float* xr = g_WihR + ch * 1024 + c * 256 + hl;
#pragma unroll
                for (int g = 0; g < 4; g++) xg[g] = xr[g * 64];
            }
            float gi = acc[i][0] + bb[0] + xg[0];
            float gf = acc[i][1] + bb[1] + xg[1];
            float gg = acc[i][2] + bb[2] + xg[2];
            float go = acc[i][3] + bb[3] + xg[3];
            float cv = sm[OFF_CS + hh * HP + b];
            float cn = sigf(gf) * cv + sigf(gi) * tanhf(gg);
            sm[OFF_CS + hh * HP + b] = cn;
            hnew[hh * HP + b] = sigf(go) * tanhf(cn);
        }
    }
    __syncthreads();
}

// ---------------- logits + log_softmax stats + gumbel sampling ----------------
__device__ __forceinline__ void sample_step(float* sm, const float* hcur,
        const float* __restrict__ Wv, const float* __restrict__ bv,
        float* __restrict__ out, int t, int base, int tid,
        unsigned int sk0, unsigned int sk1)
{
    const int sbg = tid >> 6;
    const int v = tid & 63;
    const int lane = tid & 31;
    const int wh = (tid >> 5) & 1;
    const int b0 = sbg * 7;
    int* si = (int*)sm;

    float lacc[7];
#pragma unroll
    for (int i = 0; i < 7; i++) lacc[i] = bv[v];

    for (int kc = 0; kc < 2; kc++) {
        // load W_v k-chunk [64 v][128 k] into smem as [kk][v] stride 65
        for (int idx = tid; idx < 64 * 32; idx += NT) {
            int vv = idx >> 5, f4 = idx & 31;
            float4 a = ((const float4*)(Wv + vv * 256 + kc * 128))[f4];
            sm[OFF_WT + (f4*4+0)*65 + vv] = a.x;
            sm[OFF_WT + (f4*4+1)*65 + vv] = a.y;
            sm[OFF_WT + (f4*4+2)*65 + vv] = a.z;
            sm[OFF_WT + (f4*4+3)*65 + vv] = a.w;
        }
        __syncthreads();
        const float* hk = hcur + kc * 128 * HP + b0;
        const float* wk = sm + OFF_WT + v;
#pragma unroll 8
        for (int kk = 0; kk < 128; kk++) {
            float w = wk[kk * 65];
#pragma unroll
            for (int i = 0; i < 7; i++)
                lacc[i] = fmaf(hk[kk * HP + i], w, lacc[i]);
        }
        __syncthreads();
    }

    for (int i = 0; i < 7; i++) {
        float la = lacc[i];
        int gb = base + b0 + i;
        // max over 64
        float wm = la;
#pragma unroll
        for (int o = 16; o; o >>= 1) wm = fmaxf(wm, __shfl_xor_sync(0xffffffffu, wm, o));
        if (lane == 0) sm[OFF_RMAX + sbg*2 + wh] = wm;
        __syncthreads();
        float m = fmaxf(sm[OFF_RMAX + sbg*2], sm[OFF_RMAX + sbg*2 + 1]);
        // sum exp
        float ws = expf(la - m);
#pragma unroll
        for (int o = 16; o; o >>= 1) ws += __shfl_xor_sync(0xffffffffu, ws, o);
        if (lane == 0) sm[OFF_RSUM + sbg*2 + wh] = ws;
        __syncthreads();
        float lse = logf(sm[OFF_RSUM + sbg*2] + sm[OFF_RSUM + sbg*2 + 1]);
        float logp = (la - m) - lse;
        sm[OFF_LOGP + sbg*64 + v] = logp;
        float pt = expf(logp) * logp;
#pragma unroll
        for (int o = 16; o; o >>= 1) pt += __shfl_xor_sync(0xffffffffu, pt, o);
        if (lane == 0) sm[OFF_RPLP + sbg*2 + wh] = pt;
        // gumbel noise (identical to round-1 formula)
        uint32_t o0, o1;
        threefry2x32(sk0, sk1, 0u, (uint32_t)(gb * NV + v), o0, o1);
        uint32_t bits = o0 ^ o1;
        float f = __uint_as_float((bits >> 9) | 0x3f800000u) - 1.0f;
        const float TINY = 1.17549435e-38f;
        float u = fmaxf(TINY, f * (1.0f - TINY) + TINY);
        float g = -logf(-logf(u));
        float z = la + g;
        int idx = v;
#pragma unroll
        for (int o = 16; o; o >>= 1) {
            float oz = __shfl_xor_sync(0xffffffffu, z, o);
            int   oi = __shfl_xor_sync(0xffffffffu, idx, o);
            if (oz > z || (oz == z && oi < idx)) { z = oz; idx = oi; }
        }
        if (lane == 0) { sm[OFF_RZ + sbg*2 + wh] = z; si[OFF_RI + sbg*2 + wh] = idx; }
        __syncthreads();
        if (v == 0) {
            float z0 = sm[OFF_RZ + sbg*2], z1 = sm[OFF_RZ + sbg*2 + 1];
            int i0 = si[OFF_RI + sbg*2], i1 = si[OFF_RI + sbg*2 + 1];
            int chb;
            if (z1 > z0) chb = i1;
            else if (z0 > z1) chb = i0;
            else chb = min(i0, i1);
            si[OFF_CH + b0 + i] = chb;
            float lp = sm[OFF_LOGP + sbg*64 + chb];
            sm[OFF_SLP + b0 + i] += lp;
            sm[OFF_PLP + b0 + i] += sm[OFF_RPLP + sbg*2] + sm[OFF_RPLP + sbg*2 + 1];
            sm[OFF_EP  + b0 + i] *= expf(lp);
            if (gb < NB) out[(size_t)gb * NL + t] = (float)chb;
        }
        __syncthreads();
    }
}

// ---------------- fully fused persistent rollout kernel ----------------
__global__ __launch_bounds__(NT, 1) void sender_kernel(
    const float* __restrict__ attr, const float* __restrict__ Wv,
    const float* __restrict__ bv,   const float* __restrict__ ba,
    float* __restrict__ out, Keys keys)
{
    extern __shared__ float sm[];
    const int tid = threadIdx.x;
    const int bq = tid >> 6;
    const int hl = tid & 63;
    const int base = blockIdx.x * NBR;
    const int b0 = bq * 7;

    // init c = 0, per-row accumulators
    for (int i = tid; i < NH * HP; i += NT) sm[OFF_CS + i] = 0.0f;
    if (tid < NBR) { sm[OFF_SLP + tid] = 0.0f; sm[OFF_PLP + tid] = 0.0f; sm[OFF_EP + tid] = 1.0f; }

    // load attr tile into hB region as [k][b] (k < 128)
    for (int idx = tid; idx < NBR * 32; idx += NT) {
        int b = idx >> 5, f4 = idx & 31;
        int gb = base + b;
        float4 a = make_float4(0.f, 0.f, 0.f, 0.f);
        if (gb < NB) a = ((const float4*)attr)[(size_t)gb * 32 + f4];
        sm[OFF_HB + (f4*4+0)*HP + b] = a.x;
        sm[OFF_HB + (f4*4+1)*HP + b] = a.y;
        sm[OFF_HB + (f4*4+2)*HP + b] = a.z;
        sm[OFF_HB + (f4*4+3)*HP + b] = a.w;
    }
    __syncthreads();

    // h0 = attr @ W_a^T + b_a  -> hA
    for (int c = 0; c < 4; c++) {
        int hh = c * 64 + hl;
        float acc[7] = {0,0,0,0,0,0,0};
        const float* wr = g_WaR + c * 8192 + hl;
#pragma unroll 4
        for (int k = 0; k < NA; k++) {
            float w = wr[k * 64];
#pragma unroll
            for (int i = 0; i < 7; i++)
                acc[i] = fmaf(sm[OFF_HB + k * HP + b0 + i], w, acc[i]);
        }
        float bb = ba[hh];
#pragma unroll
        for (int i = 0; i < 7; i++)
            sm[OFF_HA + hh * HP + b0 + i] = acc[i] + bb;
    }
    __syncthreads();

    float* hA = sm + OFF_HA;
    float* hB = sm + OFF_HB;

    // start-token step (x = 0): hA -> hB
    lstm_step(sm, hA, hB, tid, bq, hl, false);

    float* hc = hB;
    float* hn = hA;
    for (int t = 0; t < NL; t++) {
        sample_step(sm, hc, Wv, bv, out, t, base, tid, keys.a[t], keys.b[t]);
        if (t < NL - 1) {
            lstm_step(sm, hc, hn, tid, bq, hl, true);
            float* tmp = hc; hc = hn; hn = tmp;
        }
    }

    __syncthreads();
    for (int i = tid; i < NBR; i += NT) {
        int gb = base + i;
        if (gb < NB) {
            out[NB*NL + gb]        = sm[OFF_SLP + i];
            out[NB*NL + NB + gb]   = sm[OFF_PLP + i];
            out[NB*NL + 2*NB + gb] = sm[OFF_EP + i];
        }
    }
}

// ---------------- launcher ----------------
extern "C" void kernel_launch(void* const* d_in, const int* in_sizes, int n_in,
                              void* d_out, int out_size)
{
    const float* attr = (const float*)d_in[0];
    const float* W_a  = (const float*)d_in[1];
    const float* b_a  = (const float*)d_in[2];
    const float* W_ih = (const float*)d_in[3];
    const float* W_hh = (const float*)d_in[4];
    const float* b_ih = (const float*)d_in[5];
    const float* b_hh = (const float*)d_in[6];
    const float* W_v  = (const float*)d_in[7];
    const float* b_v  = (const float*)d_in[8];
    float* out = (float*)d_out;

    // subkeys: subkey_t = threefry(key(42)=(0,42), (0,t))
    Keys keys;
    for (int t = 0; t < NL; t++) {
        uint32_t s0, s1;
        threefry2x32(0u, 42u, 0u, (uint32_t)t, s0, s1);
        keys.a[t] = s0; keys.b[t] = s1;
    }

    static int smem_set = 0;
    if (!smem_set) {
        cudaFuncSetAttribute(sender_kernel, cudaFuncAttributeMaxDynamicSharedMemorySize,
                             SMEM_FLOATS * sizeof(float));
        smem_set = 1;
    }

    prep_kernel<<<(4*65536 + 255) / 256, 256>>>(W_hh, W_ih, W_a, b_ih, b_hh);
    sender_kernel<<<NBLK, NT, SMEM_FLOATS * sizeof(float)>>>(attr, W_v, b_v, b_a, out, keys);
}

// round 3
// speedup vs baseline: 5.4148x; 1.0009x over previous
#include <cuda_runtime.h>
#include <cstdint>

#define NB 8192      // batch
#define NA 128       // attr dim
#define NH 256       // hidden
#define NV 64        // vocab
#define NL 20        // rollout length
#define NBR 56       // batch rows per block
#define NBLK 147     // ceil(NB/NBR)
#define NT 512       // threads per block
#define HP 57        // padded b-stride for h/c smem

// ---- shared memory layout (float offsets) ----
#define OFF_HA 0
#define OFF_HB (NH*HP)                 // 14592
#define OFF_CS (2*NH*HP)               // 29184
#define OFF_WT (3*NH*HP)               // 43776 (8320 floats: 32x260 or 128x65)
#define OFF_LOGP (OFF_WT + 8320)       // 52096 (8 bg x 64 v)
#define OFF_RMAX (OFF_LOGP + 512)
#define OFF_RSUM (OFF_RMAX + 16)
#define OFF_RPLP (OFF_RSUM + 16)
#define OFF_RZ   (OFF_RPLP + 16)
#define OFF_RI   (OFF_RZ + 16)         // int
#define OFF_CH   (OFF_RI + 16)         // int[56]
#define OFF_SLP  (OFF_CH + 56)
#define OFF_PLP  (OFF_SLP + 56)
#define OFF_EP   (OFF_PLP + 56)
#define SMEM_FLOATS (OFF_EP + 56)      // 52912 floats = 211,648 B

// ---- reordered weight scratch (static device arrays) ----
__device__ float g_WhhR[4*65536];   // [chunk][k 256][nloc 256], nloc = gate*64+hl
__device__ float g_WihR[64*1024];   // [ch][chunk*256 + gate*64 + hl]
__device__ float g_WaR[4*8192];     // [chunk][k 128][hl 64]
__device__ float g_biasR[1024];     // [chunk*256 + gate*64 + hl] = b_ih+b_hh

struct Keys { unsigned int a[NL]; unsigned int b[NL]; };

// ---------------- Threefry-2x32 (20 rounds), matches JAX ----------------
__host__ __device__ __forceinline__ uint32_t rotl32(uint32_t x, int r) {
    return (x << r) | (x >> (32 - r));
}
__host__ __device__ __forceinline__ void threefry2x32(
    uint32_t k0, uint32_t k1, uint32_t x0, uint32_t x1,
    uint32_t& o0, uint32_t& o1)
{
    uint32_t ks0 = k0, ks1 = k1, ks2 = k0 ^ k1 ^ 0x1BD11BDAu;
    x0 += ks0; x1 += ks1;
#define TF_RND(r) { x0 += x1; x1 = rotl32(x1, (r)); x1 ^= x0; }
    TF_RND(13) TF_RND(15) TF_RND(26) TF_RND(6)
    x0 += ks1; x1 += ks2 + 1u;
    TF_RND(17) TF_RND(29) TF_RND(16) TF_RND(24)
    x0 += ks2; x1 += ks0 + 2u;
    TF_RND(13) TF_RND(15) TF_RND(26) TF_RND(6)
    x0 += ks0; x1 += ks1 + 3u;
    TF_RND(17) TF_RND(29) TF_RND(16) TF_RND(24)
    x0 += ks1; x1 += ks2 + 4u;
    TF_RND(13) TF_RND(15) TF_RND(26) TF_RND(6)
    x0 += ks2; x1 += ks0 + 5u;
#undef TF_RND
    o0 = x0; o1 = x1;
}

__device__ __forceinline__ float sigf(float x) { return 1.0f / (1.0f + expf(-x)); }

// ---------------- prep: reorder weights for coalesced tiled access ----------------
__global__ void prep_kernel(const float* __restrict__ Whh, const float* __restrict__ Wih,
                            const float* __restrict__ Wa,  const float* __restrict__ bih,
                            const float* __restrict__ bhh)
{
    int idx = blockIdx.x * blockDim.x + threadIdx.x;
    if (idx < 4*65536) {
        int c = idx >> 16, r = idx & 65535, k = r >> 8, n = r & 255;
        int g = n >> 6, hl = n & 63;
        g_WhhR[idx] = Whh[(size_t)(g*256 + c*64 + hl) * 256 + k];
    }
    if (idx < 64*1024) {
        int ch = idx >> 10, low = idx & 1023;
        int c = low >> 8, g = (low >> 6) & 3, hl = low & 63;
        g_WihR[idx] = Wih[(size_t)(g*256 + c*64 + hl) * 64 + ch];
    }
    if (idx < 4*8192) {
        int c = idx >> 13, r = idx & 8191, k = r >> 6, hl = r & 63;
        g_WaR[idx] = Wa[(size_t)(c*64 + hl) * 128 + k];
    }
    if (idx < 1024) {
        int c = idx >> 8, g = (idx >> 6) & 3, hl = idx & 63;
        int gn = g*256 + c*64 + hl;
        g_biasR[idx] = bih[gn] + bhh[gn];
    }
}

// ---------------- one LSTM step: gates GEMM + cell update ----------------
__device__ __forceinline__ void lstm_step(float* sm, const float* hcur, float* hnew,
                                          int tid, int bq, int hl, bool hasX)
{
    const int b0 = bq * 7;
    for (int c = 0; c < 4; c++) {
        float acc[7][4];
#pragma unroll
        for (int i = 0; i < 7; i++)
#pragma unroll
            for (int g = 0; g < 4; g++) acc[i][g] = 0.0f;

        const float* Wg = g_WhhR + c * 65536;
        float4 pf[4];
#pragma unroll
        for (int s = 0; s < 4; s++) {
            int idx = tid + s * NT;
            int kk = idx >> 6, f4 = idx & 63;
            pf[s] = ((const float4*)(Wg + kk * 256))[f4];
        }
        for (int kt = 0; kt < 8; kt++) {
#pragma unroll
            for (int s = 0; s < 4; s++) {
                int idx = tid + s * NT;
                int kk = idx >> 6, f4 = idx & 63;
                ((float4*)(sm + OFF_WT))[kk * 65 + f4] = pf[s];
            }
            __syncthreads();
            if (kt < 7) {
#pragma unroll
                for (int s = 0; s < 4; s++) {
                    int idx = tid + s * NT;
                    int kk = idx >> 6, f4 = idx & 63;
                    pf[s] = ((const float4*)(Wg + ((kt + 1) * 32 + kk) * 256))[f4];
                }
            }
            const float* hk = hcur + kt * 32 * HP + b0;
            const float* wk = sm + OFF_WT + hl;
#pragma unroll 8
            for (int kk = 0; kk < 32; kk++) {
                float hv[7], wv[4];
#pragma unroll
                for (int i = 0; i < 7; i++) hv[i] = hk[kk * HP + i];
#pragma unroll
                for (int g = 0; g < 4; g++) wv[g] = wk[kk * 260 + g * 64];
#pragma unroll
                for (int i = 0; i < 7; i++)
#pragma unroll
                    for (int g = 0; g < 4; g++)
                        acc[i][g] = fmaf(hv[i], wv[g], acc[i][g]);
            }
            __syncthreads();
        }
        // epilogue: gates -> c,h for hidden units [c*64 + hl]
        const int hh = c * 64 + hl;
        float bb[4];
#pragma unroll
        for (int g = 0; g < 4; g++) bb[g] = g_biasR[c*256 + g*64 + hl];
        const int* s_ch = (const int*)sm + OFF_CH;
#pragma unroll
        for (int i = 0; i < 7; i++) {
            int b = b0 + i;
            float xg[4] = {0.f, 0.f, 0.f, 0.f};
            if (hasX) {
                int ch = s_ch[b];
                const float* xr = g_WihR + ch * 1024 + c * 256 + hl;
#pragma unroll
                for (int g = 0; g < 4; g++) xg[g] = xr[g * 64];
            }
            float gi = acc[i][0] + bb[0] + xg[0];
            float gf = acc[i][1] + bb[1] + xg[1];
            float gg = acc[i][2] + bb[2] + xg[2];
            float go = acc[i][3] + bb[3] + xg[3];
            float cv = sm[OFF_CS + hh * HP + b];
            float cn = sigf(gf) * cv + sigf(gi) * tanhf(gg);
            sm[OFF_CS + hh * HP + b] = cn;
            hnew[hh * HP + b] = sigf(go) * tanhf(cn);
        }
    }
    __syncthreads();
}

// ---------------- logits + log_softmax stats + gumbel sampling ----------------
__device__ __forceinline__ void sample_step(float* sm, const float* hcur,
        const float* __restrict__ Wv, const float* __restrict__ bv,
        float* __restrict__ out, int t, int base, int tid,
        unsigned int sk0, unsigned int sk1)
{
    const int sbg = tid >> 6;
    const int v = tid & 63;
    const int lane = tid & 31;
    const int wh = (tid >> 5) & 1;
    const int b0 = sbg * 7;
    int* si = (int*)sm;

    float lacc[7];
#pragma unroll
    for (int i = 0; i < 7; i++) lacc[i] = bv[v];

    for (int kc = 0; kc < 2; kc++) {
        // load W_v k-chunk [64 v][128 k] into smem as [kk][v] stride 65
        for (int idx = tid; idx < 64 * 32; idx += NT) {
            int vv = idx >> 5, f4 = idx & 31;
            float4 a = ((const float4*)(Wv + vv * 256 + kc * 128))[f4];
            sm[OFF_WT + (f4*4+0)*65 + vv] = a.x;
            sm[OFF_WT + (f4*4+1)*65 + vv] = a.y;
            sm[OFF_WT + (f4*4+2)*65 + vv] = a.z;
            sm[OFF_WT + (f4*4+3)*65 + vv] = a.w;
        }
        __syncthreads();
        const float* hk = hcur + kc * 128 * HP + b0;
        const float* wk = sm + OFF_WT + v;
#pragma unroll 8
        for (int kk = 0; kk < 128; kk++) {
            float w = wk[kk * 65];
#pragma unroll
            for (int i = 0; i < 7; i++)
                lacc[i] = fmaf(hk[kk * HP + i], w, lacc[i]);
        }
        __syncthreads();
    }

    for (int i = 0; i < 7; i++) {
        float la = lacc[i];
        int gb = base + b0 + i;
        // max over 64
        float wm = la;
#pragma unroll
        for (int o = 16; o; o >>= 1) wm = fmaxf(wm, __shfl_xor_sync(0xffffffffu, wm, o));
        if (lane == 0) sm[OFF_RMAX + sbg*2 + wh] = wm;
        __syncthreads();
        float m = fmaxf(sm[OFF_RMAX + sbg*2], sm[OFF_RMAX + sbg*2 + 1]);
        // sum exp
        float ws = expf(la - m);
#pragma unroll
        for (int o = 16; o; o >>= 1) ws += __shfl_xor_sync(0xffffffffu, ws, o);
        if (lane == 0) sm[OFF_RSUM + sbg*2 + wh] = ws;
        __syncthreads();
        float lse = logf(sm[OFF_RSUM + sbg*2] + sm[OFF_RSUM + sbg*2 + 1]);
        float logp = (la - m) - lse;
        sm[OFF_LOGP + sbg*64 + v] = logp;
        float pt = expf(logp) * logp;
#pragma unroll
        for (int o = 16; o; o >>= 1) pt += __shfl_xor_sync(0xffffffffu, pt, o);
        if (lane == 0) sm[OFF_RPLP + sbg*2 + wh] = pt;
        // gumbel noise (identical to round-1 formula)
        uint32_t o0, o1;
        threefry2x32(sk0, sk1, 0u, (uint32_t)(gb * NV + v), o0, o1);
        uint32_t bits = o0 ^ o1;
        float f = __uint_as_float((bits >> 9) | 0x3f800000u) - 1.0f;
        const float TINY = 1.17549435e-38f;
        float u = fmaxf(TINY, f * (1.0f - TINY) + TINY);
        float g = -logf(-logf(u));
        float z = la + g;
        int idx = v;
#pragma unroll
        for (int o = 16; o; o >>= 1) {
            float oz = __shfl_xor_sync(0xffffffffu, z, o);
            int   oi = __shfl_xor_sync(0xffffffffu, idx, o);
            if (oz > z || (oz == z && oi < idx)) { z = oz; idx = oi; }
        }
        if (lane == 0) { sm[OFF_RZ + sbg*2 + wh] = z; si[OFF_RI + sbg*2 + wh] = idx; }
        __syncthreads();
        if (v == 0) {
            float z0 = sm[OFF_RZ + sbg*2], z1 = sm[OFF_RZ + sbg*2 + 1];
            int i0 = si[OFF_RI + sbg*2], i1 = si[OFF_RI + sbg*2 + 1];
            int chb;
            if (z1 > z0) chb = i1;
            else if (z0 > z1) chb = i0;
            else chb = min(i0, i1);
            si[OFF_CH + b0 + i] = chb;
            float lp = sm[OFF_LOGP + sbg*64 + chb];
            sm[OFF_SLP + b0 + i] += lp;
            sm[OFF_PLP + b0 + i] += sm[OFF_RPLP + sbg*2] + sm[OFF_RPLP + sbg*2 + 1];
            sm[OFF_EP  + b0 + i] *= expf(lp);
            if (gb < NB) out[(size_t)gb * NL + t] = (float)chb;
        }
        __syncthreads();
    }
}

// ---------------- fully fused persistent rollout kernel ----------------
__global__ __launch_bounds__(NT, 1) void sender_kernel(
    const float* __restrict__ attr, const float* __restrict__ Wv,
    const float* __restrict__ bv,   const float* __restrict__ ba,
    float* __restrict__ out, Keys keys)
{
    extern __shared__ float sm[];
    const int tid = threadIdx.x;
    const int bq = tid >> 6;
    const int hl = tid & 63;
    const int base = blockIdx.x * NBR;
    const int b0 = bq * 7;

    // init c = 0, per-row accumulators
    for (int i = tid; i < NH * HP; i += NT) sm[OFF_CS + i] = 0.0f;
    if (tid < NBR) { sm[OFF_SLP + tid] = 0.0f; sm[OFF_PLP + tid] = 0.0f; sm[OFF_EP + tid] = 1.0f; }

    // load attr tile into hB region as [k][b] (k < 128)
    for (int idx = tid; idx < NBR * 32; idx += NT) {
        int b = idx >> 5, f4 = idx & 31;
        int gb = base + b;
        float4 a = make_float4(0.f, 0.f, 0.f, 0.f);
        if (gb < NB) a = ((const float4*)attr)[(size_t)gb * 32 + f4];
        sm[OFF_HB + (f4*4+0)*HP + b] = a.x;
        sm[OFF_HB + (f4*4+1)*HP + b] = a.y;
        sm[OFF_HB + (f4*4+2)*HP + b] = a.z;
        sm[OFF_HB + (f4*4+3)*HP + b] = a.w;
    }
    __syncthreads();

    // h0 = attr @ W_a^T + b_a  -> hA
    for (int c = 0; c < 4; c++) {
        int hh = c * 64 + hl;
        float acc[7] = {0,0,0,0,0,0,0};
        const float* wr = g_WaR + c * 8192 + hl;
#pragma unroll 4
        for (int k = 0; k < NA; k++) {
            float w = wr[k * 64];
#pragma unroll
            for (int i = 0; i < 7; i++)
                acc[i] = fmaf(sm[OFF_HB + k * HP + b0 + i], w, acc[i]);
        }
        float bb = ba[hh];
#pragma unroll
        for (int i = 0; i < 7; i++)
            sm[OFF_HA + hh * HP + b0 + i] = acc[i] + bb;
    }
    __syncthreads();

    float* hA = sm + OFF_HA;
    float* hB = sm + OFF_HB;

    // start-token step (x = 0): hA -> hB
    lstm_step(sm, hA, hB, tid, bq, hl, false);

    float* hc = hB;
    float* hn = hA;
    for (int t = 0; t < NL; t++) {
        sample_step(sm, hc, Wv, bv, out, t, base, tid, keys.a[t], keys.b[t]);
        if (t < NL - 1) {
            lstm_step(sm, hc, hn, tid, bq, hl, true);
            float* tmp = hc; hc = hn; hn = tmp;
        }
    }

    __syncthreads();
    for (int i = tid; i < NBR; i += NT) {
        int gb = base + i;
        if (gb < NB) {
            out[NB*NL + gb]        = sm[OFF_SLP + i];
            out[NB*NL + NB + gb]   = sm[OFF_PLP + i];
            out[NB*NL + 2*NB + gb] = sm[OFF_EP + i];
        }
    }
}

// ---------------- launcher ----------------
extern "C" void kernel_launch(void* const* d_in, const int* in_sizes, int n_in,
                              void* d_out, int out_size)
{
    const float* attr = (const float*)d_in[0];
    const float* W_a  = (const float*)d_in[1];
    const float* b_a  = (const float*)d_in[2];
    const float* W_ih = (const float*)d_in[3];
    const float* W_hh = (const float*)d_in[4];
    const float* b_ih = (const float*)d_in[5];
    const float* b_hh = (const float*)d_in[6];
    const float* W_v  = (const float*)d_in[7];
    const float* b_v  = (const float*)d_in[8];
    float* out = (float*)d_out;

    // subkeys: subkey_t = threefry(key(42)=(0,42), (0,t))
    Keys keys;
    for (int t = 0; t < NL; t++) {
        uint32_t s0, s1;
        threefry2x32(0u, 42u, 0u, (uint32_t)t, s0, s1);
        keys.a[t] = s0; keys.b[t] = s1;
    }

    static int smem_set = 0;
    if (!smem_set) {
        cudaFuncSetAttribute(sender_kernel, cudaFuncAttributeMaxDynamicSharedMemorySize,
                             SMEM_FLOATS * sizeof(float));
        smem_set = 1;
    }

    prep_kernel<<<(4*65536 + 255) / 256, 256>>>(W_hh, W_ih, W_a, b_ih, b_hh);
    sender_kernel<<<NBLK, NT, SMEM_FLOATS * sizeof(float)>>>(attr, W_v, b_v, b_a, out, keys);
}

// round 4
// speedup vs baseline: 6.9483x; 1.2832x over previous
#include <cuda_runtime.h>
#include <cstdint>

#define NB 8192      // batch
#define NA 128       // attr dim
#define NH 256       // hidden
#define NV 64        // vocab
#define NL 20        // rollout length
#define NBR 56       // batch rows per block
#define NBLK 147     // ceil(NB/NBR)
#define NT 512       // threads per block
#define HP 58        // padded b-stride for h smem (even for f32x2)
#define WTS 516      // W tile row stride (floats)

// ---- shared memory layout (float offsets) ----
#define OFF_HA   0
#define OFF_HB   (NH*HP)               // 14848
#define OFF_WT   (2*NH*HP)             // 29696: 16640 floats (2x8320 bufs / Wv 256x65 / attr 128x58)
#define OFF_LOGP (OFF_WT + 16640)      // 46336
#define OFF_RMAX (OFF_LOGP + 512)
#define OFF_RSUM (OFF_RMAX + 16)
#define OFF_RPLP (OFF_RSUM + 16)
#define OFF_RZ   (OFF_RPLP + 16)
#define OFF_RI   (OFF_RZ + 16)         // int
#define OFF_CH   (OFF_RI + 16)         // int[56]
#define OFF_SLP  (OFF_CH + 56)
#define OFF_PLP  (OFF_SLP + 56)
#define OFF_EP   (OFF_PLP + 56)
#define SMEM_FLOATS (OFF_EP + 56)      // 47152 floats = 188,608 B

// ---- reordered weight scratch ----
__device__ __align__(16) float  g_WhhR[2*256*512];   // [pass][k 256][n' = g*128+nl]
__device__ __align__(16) float4 g_WihR4[64*256];     // [ch][hh] -> 4 gates
__device__ __align__(16) float  g_WaR[128*256];      // [k][hh]
__device__ __align__(16) float4 g_biasR4[256];       // [hh] -> 4 gates (b_ih+b_hh)

struct Keys { unsigned int a[NL]; unsigned int b[NL]; };

typedef unsigned long long ull;

// ---------------- packed f32x2 helpers ----------------
__device__ __forceinline__ void ffma2(ull &d, ull a, ull b) {
    asm("fma.rn.f32x2 %0, %1, %2, %3;" : "=l"(d) : "l"(a), "l"(b), "l"(d));
}
__device__ __forceinline__ ull pack2(float lo, float hi) {
    ull r; asm("mov.b64 %0, {%1, %2};" : "=l"(r) : "f"(lo), "f"(hi)); return r;
}
__device__ __forceinline__ void unpack2(ull v, float &lo, float &hi) {
    asm("mov.b64 {%0, %1}, %2;" : "=f"(lo), "=f"(hi) : "l"(v));
}

// ---------------- cp.async helpers ----------------
__device__ __forceinline__ void cp16(float* dst_smem, const float* src) {
    unsigned sdst = (unsigned)__cvta_generic_to_shared(dst_smem);
    asm volatile("cp.async.cg.shared.global [%0], [%1], 16;" :: "r"(sdst), "l"(src));
}
__device__ __forceinline__ void cp_commit() { asm volatile("cp.async.commit_group;"); }
__device__ __forceinline__ void cp_wait1() { asm volatile("cp.async.wait_group 1;"); }
__device__ __forceinline__ void cp_wait0() { asm volatile("cp.async.wait_group 0;"); }

// ---------------- Threefry-2x32 (20 rounds), matches JAX ----------------
__host__ __device__ __forceinline__ uint32_t rotl32(uint32_t x, int r) {
    return (x << r) | (x >> (32 - r));
}
__host__ __device__ __forceinline__ void threefry2x32(
    uint32_t k0, uint32_t k1, uint32_t x0, uint32_t x1,
    uint32_t& o0, uint32_t& o1)
{
    uint32_t ks0 = k0, ks1 = k1, ks2 = k0 ^ k1 ^ 0x1BD11BDAu;
    x0 += ks0; x1 += ks1;
#define TF_RND(r) { x0 += x1; x1 = rotl32(x1, (r)); x1 ^= x0; }
    TF_RND(13) TF_RND(15) TF_RND(26) TF_RND(6)
    x0 += ks1; x1 += ks2 + 1u;
    TF_RND(17) TF_RND(29) TF_RND(16) TF_RND(24)
    x0 += ks2; x1 += ks0 + 2u;
    TF_RND(13) TF_RND(15) TF_RND(26) TF_RND(6)
    x0 += ks0; x1 += ks1 + 3u;
    TF_RND(17) TF_RND(29) TF_RND(16) TF_RND(24)
    x0 += ks1; x1 += ks2 + 4u;
    TF_RND(13) TF_RND(15) TF_RND(26) TF_RND(6)
    x0 += ks2; x1 += ks0 + 5u;
#undef TF_RND
    o0 = x0; o1 = x1;
}

__device__ __forceinline__ float sigf(float x) { return 1.0f / (1.0f + expf(-x)); }

// ---------------- prep: reorder weights ----------------
__global__ void prep_kernel(const float* __restrict__ Whh, const float* __restrict__ Wih,
                            const float* __restrict__ Wa,  const float* __restrict__ bih,
                            const float* __restrict__ bhh)
{
    int idx = blockIdx.x * blockDim.x + threadIdx.x;
    if (idx < 2*256*512) {
        int p = idx >> 17, rem = idx & 131071, k = rem >> 9, n = rem & 511;
        int g = n >> 7, nl = n & 127;
        g_WhhR[idx] = Whh[(size_t)(g*256 + p*128 + nl) * 256 + k];
    }
    if (idx < 64*256*4) {
        int ch = idx >> 10, hh = (idx >> 2) & 255, g = idx & 3;
        ((float*)g_WihR4)[idx] = Wih[(size_t)(g*256 + hh) * 64 + ch];
    }
    if (idx < 128*256) {
        int k = idx >> 8, hh = idx & 255;
        g_WaR[idx] = Wa[(size_t)hh * 128 + k];
    }
    if (idx < 1024) {
        int hh = idx >> 2, g = idx & 3;
        int gn = g*256 + hh;
        ((float*)g_biasR4)[idx] = bih[gn] + bhh[gn];
    }
}

// ---------------- W tile async load: 16 k rows x 512 cols ----------------
__device__ __forceinline__ void issue_tile(float* buf, const float* Wp, int kt, int tid) {
    const float* src = Wp + kt * 16 * 512;
#pragma unroll
    for (int s = 0; s < 4; s++) {
        int i = tid + s * NT;           // < 2048 float4 slots
        int kk = i >> 7, c4 = i & 127;
        cp16(buf + kk * WTS + c4 * 4, src + kk * 512 + c4 * 4);
    }
}

// ---------------- one LSTM step (gates GEMM f32x2 + cell update) ----------------
template<bool hasX>
__device__ __forceinline__ void lstm_step(float* sm, const float* hcur, float* hnew,
                                          float* cc, int tid, int nl, int b0)
{
    float* buf0 = sm + OFF_WT;
    float* buf1 = sm + OFF_WT + 8320;
#pragma unroll
    for (int p = 0; p < 2; p++) {
        const float* Wp = g_WhhR + p * 131072;
        ull acc[7][4];
#pragma unroll
        for (int i = 0; i < 7; i++)
#pragma unroll
            for (int g = 0; g < 4; g++) acc[i][g] = 0ull;

        issue_tile(buf0, Wp, 0, tid);
        cp_commit();
        for (int kt = 0; kt < 16; kt++) {
            if (kt < 15) {
                issue_tile((kt & 1) ? buf0 : buf1, Wp, kt + 1, tid);
                cp_commit();
                cp_wait1();
            } else {
                cp_wait0();
            }
            __syncthreads();
            const float* wk = ((kt & 1) ? buf1 : buf0) + nl;
            const float* hk = hcur + kt * 16 * HP + b0;
#pragma unroll
            for (int kk = 0; kk < 16; kk++) {
                float w0 = wk[kk*WTS      ];
                float w1 = wk[kk*WTS + 128];
                float w2 = wk[kk*WTS + 256];
                float w3 = wk[kk*WTS + 384];
                ull W0 = pack2(w0, w0), W1 = pack2(w1, w1);
                ull W2 = pack2(w2, w2), W3 = pack2(w3, w3);
#pragma unroll
                for (int i = 0; i < 7; i++) {
                    ull h2 = *(const ull*)(hk + kk * HP + 2 * i);
                    ffma2(acc[i][0], h2, W0);
                    ffma2(acc[i][1], h2, W1);
                    ffma2(acc[i][2], h2, W2);
                    ffma2(acc[i][3], h2, W3);
                }
            }
            __syncthreads();
        }
        // epilogue
        const int hh = p * 128 + nl;
        float4 bb = g_biasR4[hh];
        const int* s_ch = (const int*)sm + OFF_CH;
#pragma unroll
        for (int i = 0; i < 7; i++) {
            float a0[4], a1[4];
#pragma unroll
            for (int g = 0; g < 4; g++) unpack2(acc[i][g], a0[g], a1[g]);
            float hn[2];
#pragma unroll
            for (int ro = 0; ro < 2; ro++) {
                float* ar = ro ? a1 : a0;
                int b = b0 + 2 * i + ro;
                float xx = 0.f, xy = 0.f, xz = 0.f, xw = 0.f;
                if (hasX) {
                    int ch = s_ch[b];
                    float4 xg = g_WihR4[ch * 256 + hh];
                    xx = xg.x; xy = xg.y; xz = xg.z; xw = xg.w;
                }
                float gi = ar[0] + bb.x + xx;
                float gf = ar[1] + bb.y + xy;
                float gg = ar[2] + bb.z + xz;
                float go = ar[3] + bb.w + xw;
                float cv = cc[p * 14 + 2 * i + ro];
                float cn = sigf(gf) * cv + sigf(gi) * tanhf(gg);
                cc[p * 14 + 2 * i + ro] = cn;
                hn[ro] = sigf(go) * tanhf(cn);
            }
            *(ull*)(hnew + hh * HP + b0 + 2 * i) = pack2(hn[0], hn[1]);
        }
    }
    __syncthreads();
}

// ---------------- logits + softmax stats + gumbel sampling (bitwise == round 2) ----------------
__device__ __forceinline__ void sample_step(float* sm, const float* hcur,
        const float* __restrict__ Wv, const float* __restrict__ bv,
        float* __restrict__ out, int t, int base, int tid,
        unsigned int sk0, unsigned int sk1)
{
    // stage full W_v as [k 256][v] stride 65
    for (int idx = tid; idx < NV * NH; idx += NT) {
        int k = idx & 255, v = idx >> 8;
        sm[OFF_WT + k * 65 + v] = Wv[(size_t)v * NH + k];
    }
    __syncthreads();

    const int sbg = tid >> 6;
    const int v = tid & 63;
    const int lane = tid & 31;
    const int wh = (tid >> 5) & 1;
    const int b0s = sbg * 7;
    int* si = (int*)sm;

    float lacc[7];
#pragma unroll
    for (int i = 0; i < 7; i++) lacc[i] = bv[v];

    const float* wk = sm + OFF_WT + v;
    const float* hk = hcur + b0s;
#pragma unroll 8
    for (int kk = 0; kk < NH; kk++) {
        float w = wk[kk * 65];
#pragma unroll
        for (int i = 0; i < 7; i++)
            lacc[i] = fmaf(hk[kk * HP + i], w, lacc[i]);
    }

    for (int i = 0; i < 7; i++) {
        float la = lacc[i];
        int gb = base + b0s + i;
        float wm = la;
#pragma unroll
        for (int o = 16; o; o >>= 1) wm = fmaxf(wm, __shfl_xor_sync(0xffffffffu, wm, o));
        if (lane == 0) sm[OFF_RMAX + sbg*2 + wh] = wm;
        __syncthreads();
        float m = fmaxf(sm[OFF_RMAX + sbg*2], sm[OFF_RMAX + sbg*2 + 1]);
        float ws = expf(la - m);
#pragma unroll
        for (int o = 16; o; o >>= 1) ws += __shfl_xor_sync(0xffffffffu, ws, o);
        if (lane == 0) sm[OFF_RSUM + sbg*2 + wh] = ws;
        __syncthreads();
        float lse = logf(sm[OFF_RSUM + sbg*2] + sm[OFF_RSUM + sbg*2 + 1]);
        float logp = (la - m) - lse;
        sm[OFF_LOGP + sbg*64 + v] = logp;
        float pt = expf(logp) * logp;
#pragma unroll
        for (int o = 16; o; o >>= 1) pt += __shfl_xor_sync(0xffffffffu, pt, o);
        if (lane == 0) sm[OFF_RPLP + sbg*2 + wh] = pt;
        // gumbel (identical formula/order to rounds 1-2)
        uint32_t o0, o1;
        threefry2x32(sk0, sk1, 0u, (uint32_t)(gb * NV + v), o0, o1);
        uint32_t bits = o0 ^ o1;
        float f = __uint_as_float((bits >> 9) | 0x3f800000u) - 1.0f;
        const float TINY = 1.17549435e-38f;
        float u = fmaxf(TINY, f * (1.0f - TINY) + TINY);
        float g = -logf(-logf(u));
        float z = la + g;
        int idx = v;
#pragma unroll
        for (int o = 16; o; o >>= 1) {
            float oz = __shfl_xor_sync(0xffffffffu, z, o);
            int   oi = __shfl_xor_sync(0xffffffffu, idx, o);
            if (oz > z || (oz == z && oi < idx)) { z = oz; idx = oi; }
        }
        if (lane == 0) { sm[OFF_RZ + sbg*2 + wh] = z; si[OFF_RI + sbg*2 + wh] = idx; }
        __syncthreads();
        if (v == 0) {
            float z0 = sm[OFF_RZ + sbg*2], z1 = sm[OFF_RZ + sbg*2 + 1];
            int i0 = si[OFF_RI + sbg*2], i1 = si[OFF_RI + sbg*2 + 1];
            int chb;
            if (z1 > z0) chb = i1;
            else if (z0 > z1) chb = i0;
            else chb = min(i0, i1);
            si[OFF_CH + b0s + i] = chb;
            float lp = sm[OFF_LOGP + sbg*64 + chb];
            sm[OFF_SLP + b0s + i] += lp;
            sm[OFF_PLP + b0s + i] += sm[OFF_RPLP + sbg*2] + sm[OFF_RPLP + sbg*2 + 1];
            sm[OFF_EP  + b0s + i] *= expf(lp);
            if (gb < NB) out[(size_t)gb * NL + t] = (float)chb;
        }
        __syncthreads();
    }
}

// ---------------- fused persistent rollout kernel ----------------
__global__ __launch_bounds__(NT, 1) void sender_kernel(
    const float* __restrict__ attr, const float* __restrict__ Wv,
    const float* __restrict__ bv,   const float* __restrict__ ba,
    float* __restrict__ out, Keys keys)
{
    extern __shared__ float sm[];
    const int tid = threadIdx.x;
    const int bq = tid >> 7;        // 4 groups
    const int nl = tid & 127;       // 128 n-columns
    const int b0 = bq * 14;         // 14 rows (7 f32x2 pairs)
    const int base = blockIdx.x * NBR;

    float cc[28];                   // cell state in registers: [pass][14 rows]
#pragma unroll
    for (int i = 0; i < 28; i++) cc[i] = 0.0f;

    if (tid < NBR) { sm[OFF_SLP + tid] = 0.0f; sm[OFF_PLP + tid] = 0.0f; sm[OFF_EP + tid] = 1.0f; }

    // stage attr tile [k 128][b] stride HP into WT area
    for (int idx = tid; idx < NBR * 32; idx += NT) {
        int b = idx >> 5, f4 = idx & 31;
        int gb = base + b;
        float4 a = make_float4(0.f, 0.f, 0.f, 0.f);
        if (gb < NB) a = ((const float4*)attr)[(size_t)gb * 32 + f4];
        sm[OFF_WT + (f4*4+0)*HP + b] = a.x;
        sm[OFF_WT + (f4*4+1)*HP + b] = a.y;
        sm[OFF_WT + (f4*4+2)*HP + b] = a.z;
        sm[OFF_WT + (f4*4+3)*HP + b] = a.w;
    }
    __syncthreads();

    // h0 = attr @ W_a^T + b_a  (k-ascending per acc, identical arithmetic to R2)
#pragma unroll
    for (int p = 0; p < 2; p++) {
        const int hh = p * 128 + nl;
        ull acc[7];
#pragma unroll
        for (int i = 0; i < 7; i++) acc[i] = 0ull;
        const float* wr = g_WaR + hh;
        const float* ak = sm + OFF_WT + b0;
#pragma unroll 4
        for (int k = 0; k < NA; k++) {
            float w = wr[k * 256];
            ull w2 = pack2(w, w);
#pragma unroll
            for (int i = 0; i < 7; i++) {
                ull h2 = *(const ull*)(ak + k * HP + 2 * i);
                ffma2(acc[i], h2, w2);
            }
        }
        float bbv = ba[hh];
#pragma unroll
        for (int i = 0; i < 7; i++) {
            float lo, hi; unpack2(acc[i], lo, hi);
            *(ull*)(sm + OFF_HA + hh * HP + b0 + 2 * i) = pack2(lo + bbv, hi + bbv);
        }
    }
    __syncthreads();

    float* hA = sm + OFF_HA;
    float* hB = sm + OFF_HB;

    // start-token step (x = 0): hA -> hB
    lstm_step<false>(sm, hA, hB, cc, tid, nl, b0);

    float* hc = hB;
    float* hn = hA;
    for (int t = 0; t < NL; t++) {
        sample_step(sm, hc, Wv, bv, out, t, base, tid, keys.a[t], keys.b[t]);
        if (t < NL - 1) {
            lstm_step<true>(sm, hc, hn, cc, tid, nl, b0);
            float* tmp = hc; hc = hn; hn = tmp;
        }
    }

    __syncthreads();
    for (int i = tid; i < NBR; i += NT) {
        int gb = base + i;
        if (gb < NB) {
            out[NB*NL + gb]        = sm[OFF_SLP + i];
            out[NB*NL + NB + gb]   = sm[OFF_PLP + i];
            out[NB*NL + 2*NB + gb] = sm[OFF_EP + i];
        }
    }
}

// ---------------- launcher ----------------
extern "C" void kernel_launch(void* const* d_in, const int* in_sizes, int n_in,
                              void* d_out, int out_size)
{
    const float* attr = (const float*)d_in[0];
    const float* W_a  = (const float*)d_in[1];
    const float* b_a  = (const float*)d_in[2];
    const float* W_ih = (const float*)d_in[3];
    const float* W_hh = (const float*)d_in[4];
    const float* b_ih = (const float*)d_in[5];
    const float* b_hh = (const float*)d_in[6];
    const float* W_v  = (const float*)d_in[7];
    const float* b_v  = (const float*)d_in[8];
    float* out = (float*)d_out;

    Keys keys;
    for (int t = 0; t < NL; t++) {
        uint32_t s0, s1;
        threefry2x32(0u, 42u, 0u, (uint32_t)t, s0, s1);
        keys.a[t] = s0; keys.b[t] = s1;
    }

    static int smem_set = 0;
    if (!smem_set) {
        cudaFuncSetAttribute(sender_kernel, cudaFuncAttributeMaxDynamicSharedMemorySize,
                             SMEM_FLOATS * sizeof(float));
        smem_set = 1;
    }

    prep_kernel<<<1024, 256>>>(W_hh, W_ih, W_a, b_ih, b_hh);
    sender_kernel<<<NBLK, NT, SMEM_FLOATS * sizeof(float)>>>(attr, W_v, b_v, b_a, out, keys);
}

// round 5
// speedup vs baseline: 7.3859x; 1.0630x over previous
#include <cuda_runtime.h>
#include <cstdint>

#define NB 8192      // batch
#define NA 128       // attr dim
#define NH 256       // hidden
#define NV 64        // vocab
#define NL 20        // rollout length
#define NBR 56       // batch rows per block
#define NBLK 147     // ceil(NB/NBR)
#define NT 512       // threads per block
#define HP 58        // padded b-stride for h smem (even for f32x2)
#define WTS 516      // W tile row stride (floats)
#define BUFF 8320    // floats per W tile buffer

// ---- shared memory layout (float offsets) ----
#define OFF_HA   0
#define OFF_HB   (NH*HP)               // 14848
#define OFF_WT   (2*NH*HP)             // 29696: 3 tile buffers (24960 floats)
#define OFF_LG   (OFF_WT + 2*BUFF)     // logits 56 x 66 = 3696 (aliases buf2)
#define OFF_CH   (OFF_WT + 3*BUFF)     // int[56]
#define OFF_SLP  (OFF_CH + 56)
#define OFF_PLP  (OFF_SLP + 56)
#define OFF_EP   (OFF_PLP + 56)
#define SMEM_FLOATS (OFF_EP + 56)      // 54880 floats = 219,520 B

// ---- reordered weight scratch ----
__device__ __align__(16) float  g_WhhR[2*256*512];   // [pass][k 256][n' = g*128+nl]
__device__ __align__(16) float4 g_WihR4[64*256];     // [ch][hh] -> 4 gates
__device__ __align__(16) float  g_WaR[128*256];      // [k][hh]
__device__ __align__(16) float4 g_biasR4[256];       // [hh] -> 4 gates (b_ih+b_hh)

struct Keys { unsigned int a[NL]; unsigned int b[NL]; };

typedef unsigned long long ull;

// ---------------- packed f32x2 helpers ----------------
__device__ __forceinline__ void ffma2(ull &d, ull a, ull b) {
    asm("fma.rn.f32x2 %0, %1, %2, %3;" : "=l"(d) : "l"(a), "l"(b), "l"(d));
}
__device__ __forceinline__ ull pack2(float lo, float hi) {
    ull r; asm("mov.b64 %0, {%1, %2};" : "=l"(r) : "f"(lo), "f"(hi)); return r;
}
__device__ __forceinline__ void unpack2(ull v, float &lo, float &hi) {
    asm("mov.b64 {%0, %1}, %2;" : "=f"(lo), "=f"(hi) : "l"(v));
}

// ---------------- cp.async helpers ----------------
__device__ __forceinline__ void cp16(float* dst_smem, const float* src) {
    unsigned sdst = (unsigned)__cvta_generic_to_shared(dst_smem);
    asm volatile("cp.async.cg.shared.global [%0], [%1], 16;" :: "r"(sdst), "l"(src));
}
__device__ __forceinline__ void cp_commit() { asm volatile("cp.async.commit_group;"); }
__device__ __forceinline__ void cp_wait1() { asm volatile("cp.async.wait_group 1;"); }
__device__ __forceinline__ void cp_wait0() { asm volatile("cp.async.wait_group 0;"); }

// ---------------- Threefry-2x32 (20 rounds), matches JAX ----------------
__host__ __device__ __forceinline__ uint32_t rotl32(uint32_t x, int r) {
    return (x << r) | (x >> (32 - r));
}
__host__ __device__ __forceinline__ void threefry2x32(
    uint32_t k0, uint32_t k1, uint32_t x0, uint32_t x1,
    uint32_t& o0, uint32_t& o1)
{
    uint32_t ks0 = k0, ks1 = k1, ks2 = k0 ^ k1 ^ 0x1BD11BDAu;
    x0 += ks0; x1 += ks1;
#define TF_RND(r) { x0 += x1; x1 = rotl32(x1, (r)); x1 ^= x0; }
    TF_RND(13) TF_RND(15) TF_RND(26) TF_RND(6)
    x0 += ks1; x1 += ks2 + 1u;
    TF_RND(17) TF_RND(29) TF_RND(16) TF_RND(24)
    x0 += ks2; x1 += ks0 + 2u;
    TF_RND(13) TF_RND(15) TF_RND(26) TF_RND(6)
    x0 += ks0; x1 += ks1 + 3u;
    TF_RND(17) TF_RND(29) TF_RND(16) TF_RND(24)
    x0 += ks1; x1 += ks2 + 4u;
    TF_RND(13) TF_RND(15) TF_RND(26) TF_RND(6)
    x0 += ks2; x1 += ks0 + 5u;
#undef TF_RND
    o0 = x0; o1 = x1;
}

__device__ __forceinline__ float sigf(float x) { return 1.0f / (1.0f + expf(-x)); }

// gumbel from raw bits — identical formula to rounds 1-3
__device__ __forceinline__ float gumbel_from(uint32_t sk0, uint32_t sk1, uint32_t ctr) {
    uint32_t o0, o1;
    threefry2x32(sk0, sk1, 0u, ctr, o0, o1);
    uint32_t bits = o0 ^ o1;
    float f = __uint_as_float((bits >> 9) | 0x3f800000u) - 1.0f;
    const float TINY = 1.17549435e-38f;
    float u = fmaxf(TINY, f * (1.0f - TINY) + TINY);
    return -logf(-logf(u));
}

// ---------------- prep: reorder weights ----------------
__global__ void prep_kernel(const float* __restrict__ Whh, const float* __restrict__ Wih,
                            const float* __restrict__ Wa,  const float* __restrict__ bih,
                            const float* __restrict__ bhh)
{
    int idx = blockIdx.x * blockDim.x + threadIdx.x;
    if (idx < 2*256*512) {
        int p = idx >> 17, rem = idx & 131071, k = rem >> 9, n = rem & 511;
        int g = n >> 7, nl = n & 127;
        g_WhhR[idx] = Whh[(size_t)(g*256 + p*128 + nl) * 256 + k];
    }
    if (idx < 64*256*4) {
        int ch = idx >> 10, hh = (idx >> 2) & 255, g = idx & 3;
        ((float*)g_WihR4)[idx] = Wih[(size_t)(g*256 + hh) * 64 + ch];
    }
    if (idx < 128*256) {
        int k = idx >> 8, hh = idx & 255;
        g_WaR[idx] = Wa[(size_t)hh * 128 + k];
    }
    if (idx < 1024) {
        int hh = idx >> 2, g = idx & 3;
        int gn = g*256 + hh;
        ((float*)g_biasR4)[idx] = bih[gn] + bhh[gn];
    }
}

// ---------------- W tile async load: 16 k rows x 512 cols (one group) ----------------
__device__ __forceinline__ void issue_tile(float* buf, int kt, int tid) {
    const float* src = g_WhhR + (size_t)kt * 16 * 512;
#pragma unroll
    for (int s = 0; s < 4; s++) {
        int i = tid + s * NT;           // < 2048 float4 slots
        int kk = i >> 7, c4 = i & 127;
        cp16(buf + kk * WTS + c4 * 4, src + kk * 512 + c4 * 4);
    }
    cp_commit();
}

// ---------------- LSTM epilogue for one pass (identical math to R3) ----------------
template<bool hasX>
__device__ __forceinline__ void lstm_epilogue(float* sm, float* hnew, float* cc,
                                              ull (&acc)[7][4], int p, int nl, int b0)
{
    const int hh = p * 128 + nl;
    float4 bb = g_biasR4[hh];
    const int* s_ch = (const int*)sm + OFF_CH;
#pragma unroll
    for (int i = 0; i < 7; i++) {
        float a0[4], a1[4];
#pragma unroll
        for (int g = 0; g < 4; g++) unpack2(acc[i][g], a0[g], a1[g]);
        float hn[2];
#pragma unroll
        for (int ro = 0; ro < 2; ro++) {
            float* ar = ro ? a1 : a0;
            int b = b0 + 2 * i + ro;
            float xx = 0.f, xy = 0.f, xz = 0.f, xw = 0.f;
            if (hasX) {
                int ch = s_ch[b];
                float4 xg = g_WihR4[ch * 256 + hh];
                xx = xg.x; xy = xg.y; xz = xg.z; xw = xg.w;
            }
            float gi = ar[0] + bb.x + xx;
            float gf = ar[1] + bb.y + xy;
            float gg = ar[2] + bb.z + xz;
            float go = ar[3] + bb.w + xw;
            float cv = cc[p * 14 + 2 * i + ro];
            float cn = sigf(gf) * cv + sigf(gi) * tanhf(gg);
            cc[p * 14 + 2 * i + ro] = cn;
            hn[ro] = sigf(go) * tanhf(cn);
        }
        *(ull*)(hnew + hh * HP + b0 + 2 * i) = pack2(hn[0], hn[1]);
    }
}

// ---------------- one LSTM step: triple-buffered GEMM, 1 bar per k-tile ----------------
template<bool hasX>
__device__ __forceinline__ void lstm_step(float* sm, const float* hcur, float* hnew,
                                          float* cc, int tid, int nl, int b0)
{
    float* bA = sm + OFF_WT;
    float* bB = bA + BUFF;
    float* bC = bB + BUFF;

    issue_tile(bA, 0, tid);
    issue_tile(bB, 1, tid);

    ull acc[7][4];
#pragma unroll
    for (int i = 0; i < 7; i++)
#pragma unroll
        for (int g = 0; g < 4; g++) acc[i][g] = 0ull;

#pragma unroll 1
    for (int kt = 0; kt < 32; kt++) {
        if (kt < 31) cp_wait1(); else cp_wait0();
        __syncthreads();
        if (kt + 2 < 32) issue_tile(bC, kt + 2, tid);

        const float* wk = bA + nl;
        const float* hk = hcur + (kt & 15) * 16 * HP + b0;
#pragma unroll
        for (int kk = 0; kk < 16; kk++) {
            float w0 = wk[kk*WTS      ];
            float w1 = wk[kk*WTS + 128];
            float w2 = wk[kk*WTS + 256];
            float w3 = wk[kk*WTS + 384];
            ull W0 = pack2(w0, w0), W1 = pack2(w1, w1);
            ull W2 = pack2(w2, w2), W3 = pack2(w3, w3);
#pragma unroll
            for (int i = 0; i < 7; i++) {
                ull h2 = *(const ull*)(hk + kk * HP + 2 * i);
                ffma2(acc[i][0], h2, W0);
                ffma2(acc[i][1], h2, W1);
                ffma2(acc[i][2], h2, W2);
                ffma2(acc[i][3], h2, W3);
            }
        }

        if (kt == 15) {
            lstm_epilogue<hasX>(sm, hnew, cc, acc, 0, nl, b0);
#pragma unroll
            for (int i = 0; i < 7; i++)
#pragma unroll
                for (int g = 0; g < 4; g++) acc[i][g] = 0ull;
        }

        float* tmp = bA; bA = bB; bB = bC; bC = tmp;
    }
    lstm_epilogue<hasX>(sm, hnew, cc, acc, 1, nl, b0);
    __syncthreads();
}

// ---------------- sampling: logits (bit-exact) + row-parallel reductions ----------------
__device__ __forceinline__ void sample_step(float* sm, const float* hcur,
        const float* __restrict__ Wv, const float* __restrict__ bv,
        float* __restrict__ out, int t, int base, int tid,
        unsigned int sk0, unsigned int sk1)
{
    // stage W_v as [k 256][v 64] stride 65 (in tile buffers 0-1)
    for (int idx = tid; idx < NV * NH; idx += NT) {
        int k = idx & 255, v = idx >> 8;
        sm[OFF_WT + k * 65 + v] = Wv[(size_t)v * NH + k];
    }
    __syncthreads();

    // ---- logits: same per-(b,v) fmaf chain as before (bitwise identical) ----
    {
        const int sbg = tid >> 6;         // 8 groups of 7 rows
        const int v = tid & 63;
        const int b0s = sbg * 7;
        const int p0 = (sbg & 1) ? 1 : 0; // pair base (even absolute index)
        const int sc = (sbg & 1) ? 0 : 6; // leftover scalar row
        float bvv = bv[v];
        ull accp[3];
#pragma unroll
        for (int j = 0; j < 3; j++) accp[j] = pack2(bvv, bvv);
        float accs = bvv;
        const float* wk = sm + OFF_WT + v;
        const float* hk = hcur + b0s;
#pragma unroll 4
        for (int kk = 0; kk < NH; kk++) {
            float w = wk[kk * 65];
            ull w2 = pack2(w, w);
            ffma2(accp[0], *(const ull*)(hk + kk * HP + p0), w2);
            ffma2(accp[1], *(const ull*)(hk + kk * HP + p0 + 2), w2);
            ffma2(accp[2], *(const ull*)(hk + kk * HP + p0 + 4), w2);
            accs = fmaf(hk[kk * HP + sc], w, accs);
        }
#pragma unroll
        for (int j = 0; j < 3; j++) {
            float lo, hi; unpack2(accp[j], lo, hi);
            sm[OFF_LG + (b0s + p0 + 2*j    ) * 66 + v] = lo;
            sm[OFF_LG + (b0s + p0 + 2*j + 1) * 66 + v] = hi;
        }
        sm[OFF_LG + (b0s + sc) * 66 + v] = accs;
    }
    __syncthreads();

    // ---- one warp per row: all reductions via shuffles, no bars ----
    {
        const int warp = tid >> 5, lane = tid & 31;
        int* si = (int*)sm;
        for (int r = warp; r < NBR; r += 16) {
            int gb = base + r;
            float la0 = sm[OFF_LG + r * 66 + 2 * lane];
            float la1 = sm[OFF_LG + r * 66 + 2 * lane + 1];
            // max (exact, order-invariant)
            float m = fmaxf(la0, la1);
#pragma unroll
            for (int o = 16; o; o >>= 1) m = fmaxf(m, __shfl_xor_sync(0xffffffffu, m, o));
            // lse
            float S = expf(la0 - m) + expf(la1 - m);
#pragma unroll
            for (int o = 16; o; o >>= 1) S += __shfl_xor_sync(0xffffffffu, S, o);
            float lse = logf(S);
            float lp0 = (la0 - m) - lse;
            float lp1 = (la1 - m) - lse;
            // plp term
            float pt = expf(lp0) * lp0 + expf(lp1) * lp1;
#pragma unroll
            for (int o = 16; o; o >>= 1) pt += __shfl_xor_sync(0xffffffffu, pt, o);
            // gumbel-argmax (exact bits, exact compare semantics)
            float g0 = gumbel_from(sk0, sk1, (uint32_t)(gb * NV + 2 * lane));
            float g1 = gumbel_from(sk0, sk1, (uint32_t)(gb * NV + 2 * lane + 1));
            float z0 = la0 + g0, z1 = la1 + g1;
            float z; int idx;
            if (z1 > z0) { z = z1; idx = 2 * lane + 1; }
            else         { z = z0; idx = 2 * lane; }
#pragma unroll
            for (int o = 16; o; o >>= 1) {
                float oz = __shfl_xor_sync(0xffffffffu, z, o);
                int   oi = __shfl_xor_sync(0xffffffffu, idx, o);
                if (oz > z || (oz == z && oi < idx)) { z = oz; idx = oi; }
            }
            float lpA = __shfl_sync(0xffffffffu, lp0, idx >> 1);
            float lpB = __shfl_sync(0xffffffffu, lp1, idx >> 1);
            float lp = (idx & 1) ? lpB : lpA;
            if (lane == 0) {
                si[OFF_CH + r] = idx;
                sm[OFF_SLP + r] += lp;
                sm[OFF_PLP + r] += pt;
                sm[OFF_EP + r] *= expf(lp);
                if (gb < NB) out[(size_t)gb * NL + t] = (float)idx;
            }
        }
    }
    __syncthreads();
}

// ---------------- fused persistent rollout kernel ----------------
__global__ __launch_bounds__(NT, 1) void sender_kernel(
    const float* __restrict__ attr, const float* __restrict__ Wv,
    const float* __restrict__ bv,   const float* __restrict__ ba,
    float* __restrict__ out, Keys keys)
{
    extern __shared__ float sm[];
    const int tid = threadIdx.x;
    const int bq = tid >> 7;        // 4 groups
    const int nl = tid & 127;       // 128 n-columns
    const int b0 = bq * 14;         // 14 rows (7 f32x2 pairs)
    const int base = blockIdx.x * NBR;

    float cc[28];                   // cell state in registers
#pragma unroll
    for (int i = 0; i < 28; i++) cc[i] = 0.0f;

    if (tid < NBR) { sm[OFF_SLP + tid] = 0.0f; sm[OFF_PLP + tid] = 0.0f; sm[OFF_EP + tid] = 1.0f; }

    // stage attr tile [k 128][b] stride HP into WT area
    for (int idx = tid; idx < NBR * 32; idx += NT) {
        int b = idx >> 5, f4 = idx & 31;
        int gb = base + b;
        float4 a = make_float4(0.f, 0.f, 0.f, 0.f);
        if (gb < NB) a = ((const float4*)attr)[(size_t)gb * 32 + f4];
        sm[OFF_WT + (f4*4+0)*HP + b] = a.x;
        sm[OFF_WT + (f4*4+1)*HP + b] = a.y;
        sm[OFF_WT + (f4*4+2)*HP + b] = a.z;
        sm[OFF_WT + (f4*4+3)*HP + b] = a.w;
    }
    __syncthreads();

    // h0 = attr @ W_a^T + b_a  (identical arithmetic to R2/R3)
#pragma unroll
    for (int p = 0; p < 2; p++) {
        const int hh = p * 128 + nl;
        ull acc[7];
#pragma unroll
        for (int i = 0; i < 7; i++) acc[i] = 0ull;
        const float* wr = g_WaR + hh;
        const float* ak = sm + OFF_WT + b0;
#pragma unroll 4
        for (int k = 0; k < NA; k++) {
            float w = wr[k * 256];
            ull w2 = pack2(w, w);
#pragma unroll
            for (int i = 0; i < 7; i++) {
                ull h2 = *(const ull*)(ak + k * HP + 2 * i);
                ffma2(acc[i], h2, w2);
            }
        }
        float bbv = ba[hh];
#pragma unroll
        for (int i = 0; i < 7; i++) {
            float lo, hi; unpack2(acc[i], lo, hi);
            *(ull*)(sm + OFF_HA + hh * HP + b0 + 2 * i) = pack2(lo + bbv, hi + bbv);
        }
    }
    __syncthreads();

    float* hA = sm + OFF_HA;
    float* hB = sm + OFF_HB;

    // start-token step (x = 0): hA -> hB
    lstm_step<false>(sm, hA, hB, cc, tid, nl, b0);

    float* hc = hB;
    float* hn = hA;
    for (int t = 0; t < NL; t++) {
        sample_step(sm, hc, Wv, bv, out, t, base, tid, keys.a[t], keys.b[t]);
        if (t < NL - 1) {
            lstm_step<true>(sm, hc, hn, cc, tid, nl, b0);
            float* tmp = hc; hc = hn; hn = tmp;
        }
    }

    __syncthreads();
    for (int i = tid; i < NBR; i += NT) {
        int gb = base + i;
        if (gb < NB) {
            out[NB*NL + gb]        = sm[OFF_SLP + i];
            out[NB*NL + NB + gb]   = sm[OFF_PLP + i];
            out[NB*NL + 2*NB + gb] = sm[OFF_EP + i];
        }
    }
}

// ---------------- launcher ----------------
extern "C" void kernel_launch(void* const* d_in, const int* in_sizes, int n_in,
                              void* d_out, int out_size)
{
    const float* attr = (const float*)d_in[0];
    const float* W_a  = (const float*)d_in[1];
    const float* b_a  = (const float*)d_in[2];
    const float* W_ih = (const float*)d_in[3];
    const float* W_hh = (const float*)d_in[4];
    const float* b_ih = (const float*)d_in[5];
    const float* b_hh = (const float*)d_in[6];
    const float* W_v  = (const float*)d_in[7];
    const float* b_v  = (const float*)d_in[8];
    float* out = (float*)d_out;

    Keys keys;
    for (int t = 0; t < NL; t++) {
        uint32_t s0, s1;
        threefry2x32(0u, 42u, 0u, (uint32_t)t, s0, s1);
        keys.a[t] = s0; keys.b[t] = s1;
    }

    static int smem_set = 0;
    if (!smem_set) {
        cudaFuncSetAttribute(sender_kernel, cudaFuncAttributeMaxDynamicSharedMemorySize,
                             SMEM_FLOATS * sizeof(float));
        smem_set = 1;
    }

    prep_kernel<<<1024, 256>>>(W_hh, W_ih, W_a, b_ih, b_hh);
    sender_kernel<<<NBLK, NT, SMEM_FLOATS * sizeof(float)>>>(attr, W_v, b_v, b_a, out, keys);
}